// round 15
// baseline (speedup 1.0000x reference)
#include <cuda_runtime.h>
#include <cuda_bf16.h>
#include <cuda_fp16.h>
#include <cstdint>

// ---------------- problem constants ----------------
constexpr int NN  = 38000;   // nodes
constexpr int IND = 64;      // input dim
constexpr int HID = 128;
constexpr int RR  = 8;       // relations
constexpr int EE  = 200000;  // edges per relation
constexpr int NR  = 60000;   // rows
constexpr int FF  = 19;      // features per row
constexpr int NC  = 10;      // classes

// ---------------- device scratch (static, no allocation) ----------------
__device__ float  g_h0[(size_t)NN * HID];      // relu(X @ W_in + b_in)
__device__ float  g_acc1[(size_t)NN * HID];    // layer-1 output (pre-relu)
__device__ float  g_acc2[(size_t)NN * HID];    // layer-2 output (= h2)
__device__ __half g_zall[(size_t)RR * NN * HID];  // 77.8 MB, L2-resident
__device__ int    g_hist_out[RR * NN];
__device__ int    g_hist_in[RR * NN];
__device__ float  g_norm_s[RR * NN];
__device__ float  g_norm_d[RR * NN];
__device__ int    g_indptr[RR * (NN + 1)];
__device__ int    g_cursor[RR * NN];
__device__ int    g_csr_src[(size_t)RR * EE];
__device__ float  g_mean[(size_t)NR * HID];
__device__ float  g_x1[(size_t)NR * HID];
__device__ float  g_x2[(size_t)NR * HID];
__device__ int    g_mask_is_int;

// ---------------- helpers ----------------
__device__ __forceinline__ uint32_t smem_u32(const void* p) {
    uint32_t a;
    asm("{ .reg .u64 t; cvta.to.shared.u64 t, %1; cvt.u32.u64 %0, t; }" : "=r"(a) : "l"(p));
    return a;
}

__device__ __forceinline__ void cvt8(const float* f, uint4& hi, uint4& lo) {
    unsigned h[4], l[4];
#pragma unroll
    for (int i = 0; i < 4; i++) {
        float f0 = f[2 * i], f1 = f[2 * i + 1];
        __nv_bfloat16 b0 = __float2bfloat16(f0), b1 = __float2bfloat16(f1);
        __nv_bfloat16 c0 = __float2bfloat16(f0 - __bfloat162float(b0));
        __nv_bfloat16 c1 = __float2bfloat16(f1 - __bfloat162float(b1));
        h[i] = (unsigned)__bfloat16_as_ushort(b0) | ((unsigned)__bfloat16_as_ushort(b1) << 16);
        l[i] = (unsigned)__bfloat16_as_ushort(c0) | ((unsigned)__bfloat16_as_ushort(c1) << 16);
    }
    hi = make_uint4(h[0], h[1], h[2], h[3]);
    lo = make_uint4(l[0], l[1], l[2], l[3]);
}

__device__ __forceinline__ void ldsm_x4(uint32_t* r, uint32_t addr) {
    asm volatile("ldmatrix.sync.aligned.m8n8.x4.shared.b16 {%0,%1,%2,%3}, [%4];"
                 : "=r"(r[0]), "=r"(r[1]), "=r"(r[2]), "=r"(r[3]) : "r"(addr));
}
__device__ __forceinline__ void ldsm_x4_t(uint32_t* r, uint32_t addr) {
    asm volatile("ldmatrix.sync.aligned.m8n8.x4.trans.shared.b16 {%0,%1,%2,%3}, [%4];"
                 : "=r"(r[0]), "=r"(r[1]), "=r"(r[2]), "=r"(r[3]) : "r"(addr));
}
__device__ __forceinline__ void mma_bf16(float* c, const uint32_t* a, const uint32_t* b) {
    asm volatile("mma.sync.aligned.m16n8k16.row.col.f32.bf16.bf16.f32 "
                 "{%0,%1,%2,%3}, {%4,%5,%6,%7}, {%8,%9}, {%0,%1,%2,%3};"
                 : "+f"(c[0]), "+f"(c[1]), "+f"(c[2]), "+f"(c[3])
                 : "r"(a[0]), "r"(a[1]), "r"(a[2]), "r"(a[3]), "r"(b[0]), "r"(b[1]));
}

// ---------------- zero ----------------
__global__ void k_zero4(float4* p, long long n4) {
    long long i = (long long)blockIdx.x * blockDim.x + threadIdx.x;
    long long stride = (long long)gridDim.x * blockDim.x;
    float4 z = make_float4(0.f, 0.f, 0.f, 0.f);
    for (; i < n4; i += stride) p[i] = z;
}

// ---------------- mask dtype detection (bool stored as u8 vs i32) ----------
__global__ void k_detect_mask(const unsigned char* __restrict__ m) {
    __shared__ int cnt;
    if (threadIdx.x == 0) cnt = 0;
    __syncthreads();
    int local = 0;
    for (int i = threadIdx.x; i < 65536; i += blockDim.x) local += (m[i] != 0);
    atomicAdd(&cnt, local);
    __syncthreads();
    if (threadIdx.x == 0) g_mask_is_int = (cnt < 16384) ? 1 : 0;
}

// ---------------- CSR build ----------------
__global__ void k_hist(const int* __restrict__ src, const int* __restrict__ dst) {
    long long i = (long long)blockIdx.x * blockDim.x + threadIdx.x;
    if (i >= (long long)RR * EE) return;
    int r = (int)(i / EE);
    atomicAdd(&g_hist_out[r * NN + src[i]], 1);
    atomicAdd(&g_hist_in [r * NN + dst[i]], 1);
}

__global__ void k_norms() {
    int i = blockIdx.x * blockDim.x + threadIdx.x;
    if (i >= RR * NN) return;
    g_norm_s[i] = rsqrtf(fmaxf((float)g_hist_out[i], 1.f));
    g_norm_d[i] = rsqrtf(fmaxf((float)g_hist_in [i], 1.f));
}

// one block per relation: exclusive prefix sum of in-degree -> indptr + cursor
__global__ void k_scan() {
    const int r = blockIdx.x;
    const int t = threadIdx.x;
    __shared__ int buf[1024];
    __shared__ int carry;
    if (t == 0) carry = 0;
    __syncthreads();
    for (int base = 0; base < NN; base += 1024) {
        int v = (base + t < NN) ? g_hist_in[r * NN + base + t] : 0;
        buf[t] = v;
        __syncthreads();
#pragma unroll
        for (int off = 1; off < 1024; off <<= 1) {
            int x = (t >= off) ? buf[t - off] : 0;
            __syncthreads();
            buf[t] += x;
            __syncthreads();
        }
        int c = carry;
        if (base + t < NN) {
            int excl = c + buf[t] - v;
            g_indptr[r * (NN + 1) + base + t] = excl;
            g_cursor[r * NN + base + t] = excl;
        }
        __syncthreads();
        if (t == 1023) carry = c + buf[1023];
        __syncthreads();
    }
    if (t == 0) g_indptr[r * (NN + 1) + NN] = carry;
}

__global__ void k_fill(const int* __restrict__ src, const int* __restrict__ dst) {
    long long i = (long long)blockIdx.x * blockDim.x + threadIdx.x;
    if (i >= (long long)RR * EE) return;
    int r = (int)(i / EE);
    int d = dst[i];
    int pos = atomicAdd(&g_cursor[r * NN + d], 1);
    g_csr_src[(size_t)r * EE + pos] = src[i];
}

// ---------------- fused gather: acc[d] = sum_r( nd*sum_e ns*z_r[src] ) + sum_r b_r --
// one warp per destination node; loops all 8 relations; plain store, no atomics.
__global__ void k_gather_all(const __half* __restrict__ zall,
                             const int* __restrict__ csr_src, const int* __restrict__ indptr,
                             const float* __restrict__ ns, const float* __restrict__ nd,
                             const float* __restrict__ bias, float* __restrict__ acc) {
    int gw = (int)(((long long)blockIdx.x * blockDim.x + threadIdx.x) >> 5);
    if (gw >= NN) return;
    int lane = threadIdx.x & 31;
    int c0 = lane * 4;

    float4 tot = make_float4(0.f, 0.f, 0.f, 0.f);
#pragma unroll
    for (int r = 0; r < RR; r++) {
        float4 b = __ldg((const float4*)(bias + r * HID + c0));
        tot.x += b.x; tot.y += b.y; tot.z += b.z; tot.w += b.w;
    }

#pragma unroll 1
    for (int r = 0; r < RR; r++) {
        int n0 = __ldg(&indptr[r * (NN + 1) + gw]);
        int n1 = __ldg(&indptr[r * (NN + 1) + gw + 1]);
        if (n0 == n1) continue;
        const __half* zr = zall + (size_t)r * NN * HID;
        const float* nsr = ns + (size_t)r * NN;
        const int* cs = csr_src + (size_t)r * EE;
        float4 s4 = make_float4(0.f, 0.f, 0.f, 0.f);
        for (int e = n0; e < n1; e++) {
            int s = __ldg(&cs[e]);
            float w = __ldg(&nsr[s]);
            uint2 hv = __ldg((const uint2*)(zr + (size_t)s * HID + c0));
            float2 f0 = __half22float2(*(const __half2*)&hv.x);
            float2 f1 = __half22float2(*(const __half2*)&hv.y);
            s4.x += w * f0.x; s4.y += w * f0.y;
            s4.z += w * f1.x; s4.w += w * f1.y;
        }
        float ndv = __ldg(&nd[(size_t)r * NN + gw]);
        tot.x += ndv * s4.x; tot.y += ndv * s4.y;
        tot.z += ndv * s4.z; tot.w += ndv * s4.w;
    }
    *((float4*)(acc + (size_t)gw * HID) + lane) = tot;
}

// ---------------- tensor-core split-bf16 GEMM ----------------
// ZOUT=false: C[M][128] = epi(pre(A)[M][K] @ B[K][128] [+ bias])    (fp32 out)
// ZOUT=true : z_all[r] = pre(A)[M][128] @ W[r], r = blockIdx.y       (fp16 out)
// BM=128, BN=128, BK=16, 256 threads (8 warps: 2x4), 4x4 m16n8k16 tiles/warp.
template <bool RELU_EPI, bool RELU_IN, bool BIAS, bool ZOUT>
__global__ __launch_bounds__(256, 2)
void k_tmma(const float* __restrict__ A, const float* __restrict__ B,
            const float* __restrict__ bias, float* __restrict__ C,
            __half* __restrict__ Ch, int M, int K) {
    __shared__ __align__(16) unsigned char sAhi[4096];   // 128 x 16 bf16, 32B rows
    __shared__ __align__(16) unsigned char sAlo[4096];
    __shared__ __align__(16) unsigned char sBhi[8192];   // 16 x 128 bf16, 256B rows
    __shared__ __align__(16) unsigned char sBlo[8192];

    const int tid = threadIdx.x;
    const int wid = tid >> 5, lane = tid & 31;
    const int warp_m = wid & 1;
    const int warp_n = wid >> 1;
    const int m0 = blockIdx.x * 128;
    const int rrel = ZOUT ? blockIdx.y : 0;
    if (ZOUT) B += (size_t)rrel * HID * HID;

    float acc[4][4][4];
#pragma unroll
    for (int mt = 0; mt < 4; mt++)
#pragma unroll
        for (int nt = 0; nt < 4; nt++)
#pragma unroll
            for (int q = 0; q < 4; q++) acc[mt][nt][q] = 0.f;

    const int a_row  = tid >> 1;
    const int a_half = tid & 1;
    const int arow_g = m0 + a_row;
    const int b_kr   = tid >> 4;
    const int b_n0   = (tid & 15) * 8;

    const uint32_t uAhi = smem_u32(sAhi), uAlo = smem_u32(sAlo);
    const uint32_t uBhi = smem_u32(sBhi), uBlo = smem_u32(sBlo);

    uint32_t a_addr[4], b_addr[2];
#pragma unroll
    for (int mt = 0; mt < 4; mt++) {
        int row = warp_m * 64 + mt * 16 + (lane & 15);
        uint32_t byte = (uint32_t)row * 32 + (uint32_t)(lane >> 4) * 16;
        byte ^= ((uint32_t)(row >> 2) & 1u) << 4;
        a_addr[mt] = byte;
    }
#pragma unroll
    for (int p = 0; p < 2; p++) {
        int kk = lane & 15;
        int ncol = warp_n * 32 + p * 16 + ((lane >> 4) << 3);
        uint32_t byte = (uint32_t)kk * 256 + (uint32_t)ncol * 2;
        byte ^= ((uint32_t)kk & 7u) << 4;
        b_addr[p] = byte;
    }

    uint32_t sa_byte = (uint32_t)a_row * 32 + (uint32_t)a_half * 16;
    sa_byte ^= ((uint32_t)(a_row >> 2) & 1u) << 4;
    uint32_t sb_byte = (uint32_t)b_kr * 256 + (uint32_t)b_n0 * 2;
    sb_byte ^= ((uint32_t)b_kr & 7u) << 4;

    for (int k0 = 0; k0 < K; k0 += 16) {
        {
            float f[8];
            if (arow_g < M) {
                const float* ap = A + (size_t)arow_g * K + k0 + a_half * 8;
                float4 v0 = *(const float4*)ap;
                float4 v1 = *(const float4*)(ap + 4);
                f[0] = v0.x; f[1] = v0.y; f[2] = v0.z; f[3] = v0.w;
                f[4] = v1.x; f[5] = v1.y; f[6] = v1.z; f[7] = v1.w;
                if (RELU_IN) {
#pragma unroll
                    for (int i = 0; i < 8; i++) f[i] = fmaxf(f[i], 0.f);
                }
            } else {
#pragma unroll
                for (int i = 0; i < 8; i++) f[i] = 0.f;
            }
            uint4 hi, lo;
            cvt8(f, hi, lo);
            *(uint4*)(sAhi + sa_byte) = hi;
            *(uint4*)(sAlo + sa_byte) = lo;
        }
        {
            const float* bp = B + (size_t)(k0 + b_kr) * HID + b_n0;
            float f[8];
            float4 v0 = *(const float4*)bp;
            float4 v1 = *(const float4*)(bp + 4);
            f[0] = v0.x; f[1] = v0.y; f[2] = v0.z; f[3] = v0.w;
            f[4] = v1.x; f[5] = v1.y; f[6] = v1.z; f[7] = v1.w;
            uint4 hi, lo;
            cvt8(f, hi, lo);
            *(uint4*)(sBhi + sb_byte) = hi;
            *(uint4*)(sBlo + sb_byte) = lo;
        }
        __syncthreads();

        uint32_t ah[4][4], al[4][4], bh[2][4], bl[2][4];
#pragma unroll
        for (int mt = 0; mt < 4; mt++) {
            ldsm_x4(ah[mt], uAhi + a_addr[mt]);
            ldsm_x4(al[mt], uAlo + a_addr[mt]);
        }
#pragma unroll
        for (int p = 0; p < 2; p++) {
            ldsm_x4_t(bh[p], uBhi + b_addr[p]);
            ldsm_x4_t(bl[p], uBlo + b_addr[p]);
        }
#pragma unroll
        for (int mt = 0; mt < 4; mt++) {
#pragma unroll
            for (int nt = 0; nt < 4; nt++) {
                const int p = nt >> 1, w = (nt & 1) * 2;
                uint32_t bhx[2] = {bh[p][w], bh[p][w + 1]};
                uint32_t blx[2] = {bl[p][w], bl[p][w + 1]};
                mma_bf16(acc[mt][nt], ah[mt], bhx);
                mma_bf16(acc[mt][nt], ah[mt], blx);
                mma_bf16(acc[mt][nt], al[mt], bhx);
            }
        }
        __syncthreads();
    }

    // ---- epilogue ----
#pragma unroll
    for (int nt = 0; nt < 4; nt++) {
        int cc = warp_n * 32 + nt * 8 + (lane & 3) * 2;
        float b0 = 0.f, b1 = 0.f;
        if (BIAS) { b0 = __ldg(&bias[cc]); b1 = __ldg(&bias[cc + 1]); }
#pragma unroll
        for (int mt = 0; mt < 4; mt++) {
            int rg = m0 + warp_m * 64 + mt * 16 + (lane >> 2);
            float o0 = acc[mt][nt][0] + b0, o1 = acc[mt][nt][1] + b1;
            float o2 = acc[mt][nt][2] + b0, o3 = acc[mt][nt][3] + b1;
            if (RELU_EPI) {
                o0 = fmaxf(o0, 0.f); o1 = fmaxf(o1, 0.f);
                o2 = fmaxf(o2, 0.f); o3 = fmaxf(o3, 0.f);
            }
            if (ZOUT) {
                __half* zb = Ch + (size_t)rrel * NN * HID;
                if (rg < M)
                    *(__half2*)(zb + (size_t)rg * HID + cc) = __float22half2_rn(make_float2(o0, o1));
                if (rg + 8 < M)
                    *(__half2*)(zb + (size_t)(rg + 8) * HID + cc) = __float22half2_rn(make_float2(o2, o3));
            } else {
                if (rg < M)     *(float2*)(C + (size_t)rg * HID + cc)       = make_float2(o0, o1);
                if (rg + 8 < M) *(float2*)(C + (size_t)(rg + 8) * HID + cc) = make_float2(o2, o3);
            }
        }
    }
}

// ---------------- ragged masked mean: one warp per row ----------------
__global__ void k_rowmean(const float* __restrict__ h, const int* __restrict__ ridx,
                          const unsigned char* __restrict__ rmask, float* __restrict__ outm) {
    long long gtid = (long long)blockIdx.x * blockDim.x + threadIdx.x;
    long long w = gtid >> 5;
    if (w >= NR) return;
    int lane = threadIdx.x & 31;
    const int is_int = g_mask_is_int;
    const int* rmask_i = (const int*)rmask;
    float4 acc = make_float4(0.f, 0.f, 0.f, 0.f);
    float cnt = 0.f;
#pragma unroll
    for (int f = 0; f < FF; f++) {
        bool on = is_int ? (__ldg(&rmask_i[w * FF + f]) != 0) : (rmask[w * FF + f] != 0);
        if (on) {
            int idx = __ldg(&ridx[w * FF + f]);
            float4 v = __ldg((const float4*)(h + (size_t)idx * HID) + lane);
            acc.x += v.x; acc.y += v.y; acc.z += v.z; acc.w += v.w;
            cnt += 1.f;
        }
    }
    float inv = 1.f / fmaxf(cnt, 1.f);
    acc.x *= inv; acc.y *= inv; acc.z *= inv; acc.w *= inv;
    *((float4*)(outm + (size_t)w * HID) + lane) = acc;
}

// ---------------- final head: [NR][128] @ [128][10] + b (fp32) ----------------
__global__ void k_head(const float* __restrict__ X, const float* __restrict__ W,
                       const float* __restrict__ b, float* __restrict__ out) {
    long long t = (long long)blockIdx.x * blockDim.x + threadIdx.x;
    int row = (int)(t >> 4);
    int c = (int)(t & 15);
    if (row >= NR || c >= NC) return;
    const float* x = X + (size_t)row * HID;
    float acc = b[c];
#pragma unroll
    for (int k = 0; k < HID; k++) acc += x[k] * __ldg(&W[k * NC + c]);
    out[(size_t)row * NC + c] = acc;
}

// ---------------- launch ----------------
extern "C" void kernel_launch(void* const* d_in, const int* in_sizes, int n_in,
                              void* d_out, int out_size) {
    const float* node_feats = (const float*)d_in[0];
    const int*   edges_src  = (const int*)  d_in[1];
    const int*   edges_dst  = (const int*)  d_in[2];
    const int*   row_idx    = (const int*)  d_in[3];
    const unsigned char* row_mask = (const unsigned char*)d_in[4];
    const float* W_in = (const float*)d_in[5];
    const float* b_in = (const float*)d_in[6];
    const float* W1   = (const float*)d_in[7];
    const float* b1   = (const float*)d_in[8];
    const float* W2   = (const float*)d_in[9];
    const float* b2   = (const float*)d_in[10];
    const float* Wm1  = (const float*)d_in[11];
    const float* bm1  = (const float*)d_in[12];
    const float* Wm2  = (const float*)d_in[13];
    const float* bm2  = (const float*)d_in[14];
    const float* Wm3  = (const float*)d_in[15];
    const float* bm3  = (const float*)d_in[16];
    float* out = (float*)d_out;

    float *p_h0, *p_acc1, *p_acc2, *p_ns, *p_nd, *p_mean, *p_x1, *p_x2;
    __half* p_z;
    int *p_ho, *p_hi, *p_ip, *p_cs;
    cudaGetSymbolAddress((void**)&p_h0,   g_h0);
    cudaGetSymbolAddress((void**)&p_acc1, g_acc1);
    cudaGetSymbolAddress((void**)&p_acc2, g_acc2);
    cudaGetSymbolAddress((void**)&p_z,    g_zall);
    cudaGetSymbolAddress((void**)&p_ho,   g_hist_out);
    cudaGetSymbolAddress((void**)&p_hi,   g_hist_in);
    cudaGetSymbolAddress((void**)&p_ns,   g_norm_s);
    cudaGetSymbolAddress((void**)&p_nd,   g_norm_d);
    cudaGetSymbolAddress((void**)&p_ip,   g_indptr);
    cudaGetSymbolAddress((void**)&p_cs,   g_csr_src);
    cudaGetSymbolAddress((void**)&p_mean, g_mean);
    cudaGetSymbolAddress((void**)&p_x1,   g_x1);
    cudaGetSymbolAddress((void**)&p_x2,   g_x2);

    const long long deg4 = (long long)RR * NN / 4;
    const int gb_nn = (NN + 127) / 128;   // 297
    const int gb_nr = (NR + 127) / 128;   // 469
    const unsigned gat_blocks = (unsigned)(((long long)NN * 32 + 255) / 256);

    // mask dtype detection
    k_detect_mask<<<1, 256>>>(row_mask);

    // ---- CSR build (reused by both layers) + degrees/norms ----
    k_zero4<<<1024, 256>>>((float4*)p_ho, deg4);
    k_zero4<<<1024, 256>>>((float4*)p_hi, deg4);
    k_hist<<<(RR * EE + 255) / 256, 256>>>(edges_src, edges_dst);
    k_norms<<<(RR * NN + 255) / 256, 256>>>();
    k_scan<<<RR, 1024>>>();
    k_fill<<<(RR * EE + 255) / 256, 256>>>(edges_src, edges_dst);

    // input linear + relu
    k_tmma<true, false, true, false><<<gb_nn, 256>>>(
        node_feats, W_in, b_in, p_h0, nullptr, NN, IND);

    // ---- RGCN layer 1: z_all[r] = h0 @ W1_r (one launch), then fused gather
    {
        dim3 grid(gb_nn, RR);
        k_tmma<false, false, false, true><<<grid, 256>>>(
            p_h0, W1, nullptr, nullptr, p_z, NN, HID);
        k_gather_all<<<gat_blocks, 256>>>(p_z, p_cs, p_ip, p_ns, p_nd, b1, p_acc1);
    }

    // ---- RGCN layer 2: relu folded into the A-loader
    {
        dim3 grid(gb_nn, RR);
        k_tmma<false, true, false, true><<<grid, 256>>>(
            p_acc1, W2, nullptr, nullptr, p_z, NN, HID);
        k_gather_all<<<gat_blocks, 256>>>(p_z, p_cs, p_ip, p_ns, p_nd, b2, p_acc2);
    }

    // ragged masked mean over acc2 (= h2, no relu)
    {
        long long nt = (long long)NR * 32;
        k_rowmean<<<(unsigned)((nt + 255) / 256), 256>>>(p_acc2, row_idx, row_mask, p_mean);
    }

    // MLP head
    k_tmma<true, false, true, false><<<gb_nr, 256>>>(p_mean, Wm1, bm1, p_x1, nullptr, NR, HID);
    k_tmma<true, false, true, false><<<gb_nr, 256>>>(p_x1,  Wm2, bm2, p_x2, nullptr, NR, HID);
    k_head<<<(NR * 16 + 255) / 256, 256>>>(p_x2, Wm3, bm3, out);

    (void)in_sizes; (void)n_in; (void)out_size;
}

// round 17
// speedup vs baseline: 1.3900x; 1.3900x over previous
#include <cuda_runtime.h>
#include <cuda_bf16.h>
#include <cuda_fp16.h>
#include <cstdint>

// ---------------- problem constants ----------------
constexpr int NN  = 38000;   // nodes
constexpr int IND = 64;      // input dim
constexpr int HID = 128;
constexpr int RR  = 8;       // relations
constexpr int GR  = 4;       // relations per group (z stays L2-resident)
constexpr int EE  = 200000;  // edges per relation
constexpr int NR  = 60000;   // rows
constexpr int FF  = 19;      // features per row
constexpr int NC  = 10;      // classes

// ---------------- device scratch (static, no allocation) ----------------
__device__ float  g_h0[(size_t)NN * HID];
__device__ float  g_acc1[(size_t)NN * HID];
__device__ float  g_acc2[(size_t)NN * HID];
__device__ __half g_zg[(size_t)GR * NN * HID];   // 38.9 MB, L2-resident
__device__ int    g_hist_out[RR * NN];
__device__ int    g_hist_in[RR * NN];
__device__ float  g_norm_s[RR * NN];
__device__ float  g_norm_d[RR * NN];
__device__ int    g_indptr[RR * (NN + 1)];
__device__ int    g_cursor[RR * NN];
__device__ int    g_csr_src[(size_t)RR * EE];
__device__ float  g_mean[(size_t)NR * HID];
__device__ float  g_x1[(size_t)NR * HID];
__device__ float  g_x2[(size_t)NR * HID];
__device__ int    g_mask_is_int;

// ---------------- helpers ----------------
__device__ __forceinline__ uint32_t smem_u32(const void* p) {
    uint32_t a;
    asm("{ .reg .u64 t; cvta.to.shared.u64 t, %1; cvt.u32.u64 %0, t; }" : "=r"(a) : "l"(p));
    return a;
}

__device__ __forceinline__ void cvt8(const float* f, uint4& hi, uint4& lo) {
    unsigned h[4], l[4];
#pragma unroll
    for (int i = 0; i < 4; i++) {
        float f0 = f[2 * i], f1 = f[2 * i + 1];
        __nv_bfloat16 b0 = __float2bfloat16(f0), b1 = __float2bfloat16(f1);
        __nv_bfloat16 c0 = __float2bfloat16(f0 - __bfloat162float(b0));
        __nv_bfloat16 c1 = __float2bfloat16(f1 - __bfloat162float(b1));
        h[i] = (unsigned)__bfloat16_as_ushort(b0) | ((unsigned)__bfloat16_as_ushort(b1) << 16);
        l[i] = (unsigned)__bfloat16_as_ushort(c0) | ((unsigned)__bfloat16_as_ushort(c1) << 16);
    }
    hi = make_uint4(h[0], h[1], h[2], h[3]);
    lo = make_uint4(l[0], l[1], l[2], l[3]);
}

__device__ __forceinline__ void ldsm_x4(uint32_t* r, uint32_t addr) {
    asm volatile("ldmatrix.sync.aligned.m8n8.x4.shared.b16 {%0,%1,%2,%3}, [%4];"
                 : "=r"(r[0]), "=r"(r[1]), "=r"(r[2]), "=r"(r[3]) : "r"(addr));
}
__device__ __forceinline__ void ldsm_x4_t(uint32_t* r, uint32_t addr) {
    asm volatile("ldmatrix.sync.aligned.m8n8.x4.trans.shared.b16 {%0,%1,%2,%3}, [%4];"
                 : "=r"(r[0]), "=r"(r[1]), "=r"(r[2]), "=r"(r[3]) : "r"(addr));
}
__device__ __forceinline__ void mma_bf16(float* c, const uint32_t* a, const uint32_t* b) {
    asm volatile("mma.sync.aligned.m16n8k16.row.col.f32.bf16.bf16.f32 "
                 "{%0,%1,%2,%3}, {%4,%5,%6,%7}, {%8,%9}, {%0,%1,%2,%3};"
                 : "+f"(c[0]), "+f"(c[1]), "+f"(c[2]), "+f"(c[3])
                 : "r"(a[0]), "r"(a[1]), "r"(a[2]), "r"(a[3]), "r"(b[0]), "r"(b[1]));
}

// ---------------- zero ----------------
__global__ void k_zero4(float4* p, long long n4) {
    long long i = (long long)blockIdx.x * blockDim.x + threadIdx.x;
    long long stride = (long long)gridDim.x * blockDim.x;
    float4 z = make_float4(0.f, 0.f, 0.f, 0.f);
    for (; i < n4; i += stride) p[i] = z;
}

// ---------------- mask dtype detection (bool stored as u8 vs i32) ----------
__global__ void k_detect_mask(const unsigned char* __restrict__ m) {
    __shared__ int cnt;
    if (threadIdx.x == 0) cnt = 0;
    __syncthreads();
    int local = 0;
    for (int i = threadIdx.x; i < 65536; i += blockDim.x) local += (m[i] != 0);
    atomicAdd(&cnt, local);
    __syncthreads();
    if (threadIdx.x == 0) g_mask_is_int = (cnt < 16384) ? 1 : 0;
}

// ---------------- CSR build ----------------
__global__ void k_hist(const int* __restrict__ src, const int* __restrict__ dst) {
    long long i = (long long)blockIdx.x * blockDim.x + threadIdx.x;
    if (i >= (long long)RR * EE) return;
    int r = (int)(i / EE);
    atomicAdd(&g_hist_out[r * NN + src[i]], 1);
    atomicAdd(&g_hist_in [r * NN + dst[i]], 1);
}

__global__ void k_norms() {
    int i = blockIdx.x * blockDim.x + threadIdx.x;
    if (i >= RR * NN) return;
    g_norm_s[i] = rsqrtf(fmaxf((float)g_hist_out[i], 1.f));
    g_norm_d[i] = rsqrtf(fmaxf((float)g_hist_in [i], 1.f));
}

// one block per relation: exclusive prefix sum of in-degree -> indptr + cursor
__global__ void k_scan() {
    const int r = blockIdx.x;
    const int t = threadIdx.x;
    __shared__ int buf[1024];
    __shared__ int carry;
    if (t == 0) carry = 0;
    __syncthreads();
    for (int base = 0; base < NN; base += 1024) {
        int v = (base + t < NN) ? g_hist_in[r * NN + base + t] : 0;
        buf[t] = v;
        __syncthreads();
#pragma unroll
        for (int off = 1; off < 1024; off <<= 1) {
            int x = (t >= off) ? buf[t - off] : 0;
            __syncthreads();
            buf[t] += x;
            __syncthreads();
        }
        int c = carry;
        if (base + t < NN) {
            int excl = c + buf[t] - v;
            g_indptr[r * (NN + 1) + base + t] = excl;
            g_cursor[r * NN + base + t] = excl;
        }
        __syncthreads();
        if (t == 1023) carry = c + buf[1023];
        __syncthreads();
    }
    if (t == 0) g_indptr[r * (NN + 1) + NN] = carry;
}

__global__ void k_fill(const int* __restrict__ src, const int* __restrict__ dst) {
    long long i = (long long)blockIdx.x * blockDim.x + threadIdx.x;
    if (i >= (long long)RR * EE) return;
    int r = (int)(i / EE);
    int d = dst[i];
    int pos = atomicAdd(&g_cursor[r * NN + d], 1);
    g_csr_src[(size_t)r * EE + pos] = src[i];
}

// ---------------- grouped gather ----------------
// acc[d] (+)= sum_{rr in group} nd_r[d] * sum_e ns_r[src]*z_rr[src]
// FIRST group also initializes with sum_r bias_r; one warp per dst, no atomics.
template <bool FIRST>
__global__ void k_gather_grp(const __half* __restrict__ zg,
                             const int* __restrict__ csr_src, const int* __restrict__ indptr,
                             const float* __restrict__ ns, const float* __restrict__ nd,
                             const float* __restrict__ bias, float* __restrict__ acc,
                             int rbase) {
    int gw = (int)(((long long)blockIdx.x * blockDim.x + threadIdx.x) >> 5);
    if (gw >= NN) return;
    int lane = threadIdx.x & 31;
    int c0 = lane * 4;

    float4 tot;
    if (FIRST) {
        tot = make_float4(0.f, 0.f, 0.f, 0.f);
#pragma unroll
        for (int r = 0; r < RR; r++) {
            float4 b = __ldg((const float4*)(bias + r * HID + c0));
            tot.x += b.x; tot.y += b.y; tot.z += b.z; tot.w += b.w;
        }
    } else {
        tot = *((float4*)(acc + (size_t)gw * HID) + lane);
    }

#pragma unroll 1
    for (int rr = 0; rr < GR; rr++) {
        int r = rbase + rr;
        int n0 = __ldg(&indptr[r * (NN + 1) + gw]);
        int n1 = __ldg(&indptr[r * (NN + 1) + gw + 1]);
        if (n0 == n1) continue;
        const __half* zr = zg + (size_t)rr * NN * HID;
        const float* nsr = ns + (size_t)r * NN;
        const int* cs = csr_src + (size_t)r * EE;
        float4 s4 = make_float4(0.f, 0.f, 0.f, 0.f);
        int e = n0;
        for (; e + 1 < n1; e += 2) {
            int s0 = __ldg(&cs[e]);
            int s1 = __ldg(&cs[e + 1]);
            float w0 = __ldg(&nsr[s0]);
            float w1 = __ldg(&nsr[s1]);
            uint2 h0 = __ldg((const uint2*)(zr + (size_t)s0 * HID + c0));
            uint2 h1 = __ldg((const uint2*)(zr + (size_t)s1 * HID + c0));
            float2 a0 = __half22float2(*(const __half2*)&h0.x);
            float2 a1 = __half22float2(*(const __half2*)&h0.y);
            float2 b0 = __half22float2(*(const __half2*)&h1.x);
            float2 b1 = __half22float2(*(const __half2*)&h1.y);
            s4.x += w0 * a0.x + w1 * b0.x;
            s4.y += w0 * a0.y + w1 * b0.y;
            s4.z += w0 * a1.x + w1 * b1.x;
            s4.w += w0 * a1.y + w1 * b1.y;
        }
        if (e < n1) {
            int s0 = __ldg(&cs[e]);
            float w0 = __ldg(&nsr[s0]);
            uint2 h0 = __ldg((const uint2*)(zr + (size_t)s0 * HID + c0));
            float2 a0 = __half22float2(*(const __half2*)&h0.x);
            float2 a1 = __half22float2(*(const __half2*)&h0.y);
            s4.x += w0 * a0.x; s4.y += w0 * a0.y;
            s4.z += w0 * a1.x; s4.w += w0 * a1.y;
        }
        float ndv = __ldg(&nd[(size_t)r * NN + gw]);
        tot.x += ndv * s4.x; tot.y += ndv * s4.y;
        tot.z += ndv * s4.z; tot.w += ndv * s4.w;
    }
    *((float4*)(acc + (size_t)gw * HID) + lane) = tot;
}

// ---------------- tensor-core split-bf16 GEMM ----------------
// ZOUT=false: C[M][128] = epi(pre(A)[M][K] @ B[K][128] [+ bias])    (fp32 out)
// ZOUT=true : z_grp[y] = pre(A)[M][128] @ W[y], y = blockIdx.y       (fp16 out)
// BM=128, BN=128, BK=16, 256 threads (8 warps: 2x4), 4x4 m16n8k16 tiles/warp.
template <bool RELU_EPI, bool RELU_IN, bool BIAS, bool ZOUT>
__global__ __launch_bounds__(256, 2)
void k_tmma(const float* __restrict__ A, const float* __restrict__ B,
            const float* __restrict__ bias, float* __restrict__ C,
            __half* __restrict__ Ch, int M, int K) {
    __shared__ __align__(16) unsigned char sAhi[4096];
    __shared__ __align__(16) unsigned char sAlo[4096];
    __shared__ __align__(16) unsigned char sBhi[8192];
    __shared__ __align__(16) unsigned char sBlo[8192];

    const int tid = threadIdx.x;
    const int wid = tid >> 5, lane = tid & 31;
    const int warp_m = wid & 1;
    const int warp_n = wid >> 1;
    const int m0 = blockIdx.x * 128;
    const int yrel = ZOUT ? blockIdx.y : 0;
    if (ZOUT) B += (size_t)yrel * HID * HID;

    float acc[4][4][4];
#pragma unroll
    for (int mt = 0; mt < 4; mt++)
#pragma unroll
        for (int nt = 0; nt < 4; nt++)
#pragma unroll
            for (int q = 0; q < 4; q++) acc[mt][nt][q] = 0.f;

    const int a_row  = tid >> 1;
    const int a_half = tid & 1;
    const int arow_g = m0 + a_row;
    const int b_kr   = tid >> 4;
    const int b_n0   = (tid & 15) * 8;

    const uint32_t uAhi = smem_u32(sAhi), uAlo = smem_u32(sAlo);
    const uint32_t uBhi = smem_u32(sBhi), uBlo = smem_u32(sBlo);

    uint32_t a_addr[4], b_addr[2];
#pragma unroll
    for (int mt = 0; mt < 4; mt++) {
        int row = warp_m * 64 + mt * 16 + (lane & 15);
        uint32_t byte = (uint32_t)row * 32 + (uint32_t)(lane >> 4) * 16;
        byte ^= ((uint32_t)(row >> 2) & 1u) << 4;
        a_addr[mt] = byte;
    }
#pragma unroll
    for (int p = 0; p < 2; p++) {
        int kk = lane & 15;
        int ncol = warp_n * 32 + p * 16 + ((lane >> 4) << 3);
        uint32_t byte = (uint32_t)kk * 256 + (uint32_t)ncol * 2;
        byte ^= ((uint32_t)kk & 7u) << 4;
        b_addr[p] = byte;
    }

    uint32_t sa_byte = (uint32_t)a_row * 32 + (uint32_t)a_half * 16;
    sa_byte ^= ((uint32_t)(a_row >> 2) & 1u) << 4;
    uint32_t sb_byte = (uint32_t)b_kr * 256 + (uint32_t)b_n0 * 2;
    sb_byte ^= ((uint32_t)b_kr & 7u) << 4;

    for (int k0 = 0; k0 < K; k0 += 16) {
        {
            float f[8];
            if (arow_g < M) {
                const float* ap = A + (size_t)arow_g * K + k0 + a_half * 8;
                float4 v0 = *(const float4*)ap;
                float4 v1 = *(const float4*)(ap + 4);
                f[0] = v0.x; f[1] = v0.y; f[2] = v0.z; f[3] = v0.w;
                f[4] = v1.x; f[5] = v1.y; f[6] = v1.z; f[7] = v1.w;
                if (RELU_IN) {
#pragma unroll
                    for (int i = 0; i < 8; i++) f[i] = fmaxf(f[i], 0.f);
                }
            } else {
#pragma unroll
                for (int i = 0; i < 8; i++) f[i] = 0.f;
            }
            uint4 hi, lo;
            cvt8(f, hi, lo);
            *(uint4*)(sAhi + sa_byte) = hi;
            *(uint4*)(sAlo + sa_byte) = lo;
        }
        {
            const float* bp = B + (size_t)(k0 + b_kr) * HID + b_n0;
            float f[8];
            float4 v0 = *(const float4*)bp;
            float4 v1 = *(const float4*)(bp + 4);
            f[0] = v0.x; f[1] = v0.y; f[2] = v0.z; f[3] = v0.w;
            f[4] = v1.x; f[5] = v1.y; f[6] = v1.z; f[7] = v1.w;
            uint4 hi, lo;
            cvt8(f, hi, lo);
            *(uint4*)(sBhi + sb_byte) = hi;
            *(uint4*)(sBlo + sb_byte) = lo;
        }
        __syncthreads();

        uint32_t ah[4][4], al[4][4], bh[2][4], bl[2][4];
#pragma unroll
        for (int mt = 0; mt < 4; mt++) {
            ldsm_x4(ah[mt], uAhi + a_addr[mt]);
            ldsm_x4(al[mt], uAlo + a_addr[mt]);
        }
#pragma unroll
        for (int p = 0; p < 2; p++) {
            ldsm_x4_t(bh[p], uBhi + b_addr[p]);
            ldsm_x4_t(bl[p], uBlo + b_addr[p]);
        }
#pragma unroll
        for (int mt = 0; mt < 4; mt++) {
#pragma unroll
            for (int nt = 0; nt < 4; nt++) {
                const int p = nt >> 1, w = (nt & 1) * 2;
                uint32_t bhx[2] = {bh[p][w], bh[p][w + 1]};
                uint32_t blx[2] = {bl[p][w], bl[p][w + 1]};
                mma_bf16(acc[mt][nt], ah[mt], bhx);
                mma_bf16(acc[mt][nt], ah[mt], blx);
                mma_bf16(acc[mt][nt], al[mt], bhx);
            }
        }
        __syncthreads();
    }

#pragma unroll
    for (int nt = 0; nt < 4; nt++) {
        int cc = warp_n * 32 + nt * 8 + (lane & 3) * 2;
        float b0 = 0.f, b1 = 0.f;
        if (BIAS) { b0 = __ldg(&bias[cc]); b1 = __ldg(&bias[cc + 1]); }
#pragma unroll
        for (int mt = 0; mt < 4; mt++) {
            int rg = m0 + warp_m * 64 + mt * 16 + (lane >> 2);
            float o0 = acc[mt][nt][0] + b0, o1 = acc[mt][nt][1] + b1;
            float o2 = acc[mt][nt][2] + b0, o3 = acc[mt][nt][3] + b1;
            if (RELU_EPI) {
                o0 = fmaxf(o0, 0.f); o1 = fmaxf(o1, 0.f);
                o2 = fmaxf(o2, 0.f); o3 = fmaxf(o3, 0.f);
            }
            if (ZOUT) {
                __half* zb = Ch + (size_t)yrel * NN * HID;
                if (rg < M)
                    *(__half2*)(zb + (size_t)rg * HID + cc) = __float22half2_rn(make_float2(o0, o1));
                if (rg + 8 < M)
                    *(__half2*)(zb + (size_t)(rg + 8) * HID + cc) = __float22half2_rn(make_float2(o2, o3));
            } else {
                if (rg < M)     *(float2*)(C + (size_t)rg * HID + cc)       = make_float2(o0, o1);
                if (rg + 8 < M) *(float2*)(C + (size_t)(rg + 8) * HID + cc) = make_float2(o2, o3);
            }
        }
    }
}

// ---------------- ragged masked mean: one warp per row ----------------
__global__ void k_rowmean(const float* __restrict__ h, const int* __restrict__ ridx,
                          const unsigned char* __restrict__ rmask, float* __restrict__ outm) {
    long long gtid = (long long)blockIdx.x * blockDim.x + threadIdx.x;
    long long w = gtid >> 5;
    if (w >= NR) return;
    int lane = threadIdx.x & 31;
    const int is_int = g_mask_is_int;
    const int* rmask_i = (const int*)rmask;
    float4 acc = make_float4(0.f, 0.f, 0.f, 0.f);
    float cnt = 0.f;
#pragma unroll
    for (int f = 0; f < FF; f++) {
        bool on = is_int ? (__ldg(&rmask_i[w * FF + f]) != 0) : (rmask[w * FF + f] != 0);
        if (on) {
            int idx = __ldg(&ridx[w * FF + f]);
            float4 v = __ldg((const float4*)(h + (size_t)idx * HID) + lane);
            acc.x += v.x; acc.y += v.y; acc.z += v.z; acc.w += v.w;
            cnt += 1.f;
        }
    }
    float inv = 1.f / fmaxf(cnt, 1.f);
    acc.x *= inv; acc.y *= inv; acc.z *= inv; acc.w *= inv;
    *((float4*)(outm + (size_t)w * HID) + lane) = acc;
}

// ---------------- final head: [NR][128] @ [128][10] + b (fp32) ----------------
__global__ void k_head(const float* __restrict__ X, const float* __restrict__ W,
                       const float* __restrict__ b, float* __restrict__ out) {
    long long t = (long long)blockIdx.x * blockDim.x + threadIdx.x;
    int row = (int)(t >> 4);
    int c = (int)(t & 15);
    if (row >= NR || c >= NC) return;
    const float* x = X + (size_t)row * HID;
    float acc = b[c];
#pragma unroll
    for (int k = 0; k < HID; k++) acc += x[k] * __ldg(&W[k * NC + c]);
    out[(size_t)row * NC + c] = acc;
}

// ---------------- launch ----------------
extern "C" void kernel_launch(void* const* d_in, const int* in_sizes, int n_in,
                              void* d_out, int out_size) {
    const float* node_feats = (const float*)d_in[0];
    const int*   edges_src  = (const int*)  d_in[1];
    const int*   edges_dst  = (const int*)  d_in[2];
    const int*   row_idx    = (const int*)  d_in[3];
    const unsigned char* row_mask = (const unsigned char*)d_in[4];
    const float* W_in = (const float*)d_in[5];
    const float* b_in = (const float*)d_in[6];
    const float* W1   = (const float*)d_in[7];
    const float* b1   = (const float*)d_in[8];
    const float* W2   = (const float*)d_in[9];
    const float* b2   = (const float*)d_in[10];
    const float* Wm1  = (const float*)d_in[11];
    const float* bm1  = (const float*)d_in[12];
    const float* Wm2  = (const float*)d_in[13];
    const float* bm2  = (const float*)d_in[14];
    const float* Wm3  = (const float*)d_in[15];
    const float* bm3  = (const float*)d_in[16];
    float* out = (float*)d_out;

    float *p_h0, *p_acc1, *p_acc2, *p_ns, *p_nd, *p_mean, *p_x1, *p_x2;
    __half* p_z;
    int *p_ho, *p_hi, *p_ip, *p_cs;
    cudaGetSymbolAddress((void**)&p_h0,   g_h0);
    cudaGetSymbolAddress((void**)&p_acc1, g_acc1);
    cudaGetSymbolAddress((void**)&p_acc2, g_acc2);
    cudaGetSymbolAddress((void**)&p_z,    g_zg);
    cudaGetSymbolAddress((void**)&p_ho,   g_hist_out);
    cudaGetSymbolAddress((void**)&p_hi,   g_hist_in);
    cudaGetSymbolAddress((void**)&p_ns,   g_norm_s);
    cudaGetSymbolAddress((void**)&p_nd,   g_norm_d);
    cudaGetSymbolAddress((void**)&p_ip,   g_indptr);
    cudaGetSymbolAddress((void**)&p_cs,   g_csr_src);
    cudaGetSymbolAddress((void**)&p_mean, g_mean);
    cudaGetSymbolAddress((void**)&p_x1,   g_x1);
    cudaGetSymbolAddress((void**)&p_x2,   g_x2);

    const long long deg4 = (long long)RR * NN / 4;
    const int gb_nn = (NN + 127) / 128;   // 297
    const int gb_nr = (NR + 127) / 128;   // 469
    const unsigned gat_blocks = (unsigned)(((long long)NN * 32 + 255) / 256);

    // mask dtype detection
    k_detect_mask<<<1, 256>>>(row_mask);

    // ---- CSR build (reused by both layers) + degrees/norms ----
    k_zero4<<<1024, 256>>>((float4*)p_ho, deg4);
    k_zero4<<<1024, 256>>>((float4*)p_hi, deg4);
    k_hist<<<(RR * EE + 255) / 256, 256>>>(edges_src, edges_dst);
    k_norms<<<(RR * NN + 255) / 256, 256>>>();
    k_scan<<<RR, 1024>>>();
    k_fill<<<(RR * EE + 255) / 256, 256>>>(edges_src, edges_dst);

    // input linear + relu
    k_tmma<true, false, true, false><<<gb_nn, 256>>>(
        node_feats, W_in, b_in, p_h0, nullptr, NN, IND);

    // ---- RGCN layer 1 (two relation-groups of 4) ----
    {
        dim3 grid(gb_nn, GR);
        k_tmma<false, false, false, true><<<grid, 256>>>(
            p_h0, W1, nullptr, nullptr, p_z, NN, HID);
        k_gather_grp<true><<<gat_blocks, 256>>>(p_z, p_cs, p_ip, p_ns, p_nd, b1, p_acc1, 0);
        k_tmma<false, false, false, true><<<grid, 256>>>(
            p_h0, W1 + (size_t)GR * HID * HID, nullptr, nullptr, p_z, NN, HID);
        k_gather_grp<false><<<gat_blocks, 256>>>(p_z, p_cs, p_ip, p_ns, p_nd, b1, p_acc1, GR);
    }

    // ---- RGCN layer 2 (relu folded into A-loader) ----
    {
        dim3 grid(gb_nn, GR);
        k_tmma<false, true, false, true><<<grid, 256>>>(
            p_acc1, W2, nullptr, nullptr, p_z, NN, HID);
        k_gather_grp<true><<<gat_blocks, 256>>>(p_z, p_cs, p_ip, p_ns, p_nd, b2, p_acc2, 0);
        k_tmma<false, true, false, true><<<grid, 256>>>(
            p_acc1, W2 + (size_t)GR * HID * HID, nullptr, nullptr, p_z, NN, HID);
        k_gather_grp<false><<<gat_blocks, 256>>>(p_z, p_cs, p_ip, p_ns, p_nd, b2, p_acc2, GR);
    }

    // ragged masked mean over acc2 (= h2, no relu)
    {
        long long nt = (long long)NR * 32;
        k_rowmean<<<(unsigned)((nt + 255) / 256), 256>>>(p_acc2, row_idx, row_mask, p_mean);
    }

    // MLP head
    k_tmma<true, false, true, false><<<gb_nr, 256>>>(p_mean, Wm1, bm1, p_x1, nullptr, NR, HID);
    k_tmma<true, false, true, false><<<gb_nr, 256>>>(p_x1,  Wm2, bm2, p_x2, nullptr, NR, HID);
    k_head<<<(NR * 16 + 255) / 256, 256>>>(p_x2, Wm3, bm3, out);

    (void)in_sizes; (void)n_in; (void)out_size;
}